// round 17
// baseline (speedup 1.0000x reference)
#include <cuda_runtime.h>
#include <math.h>

// DYAN FISTA sparse coding — parity-butterfly, warp-specialized
// producer/consumer ping-pong over column halves.
//   x: [2,36,20480] f32; Drr/Dtheta: [40] f32; out: [2,161,20480] f32
//
// Round-17 vs round-16 (same per-column math, overlapped schedule):
//  - columns split into halves A (ull 0..23) and B (24..47). 4 producer
//    warps compute V for half (s&1) at step s while 6+6 consumer warps
//    (warp-aligned per half) run E/O + epilogue for the other half.
//    201 steps, one __syncthreads each (same barrier count as before),
//    disjoint SMEM per half -> no double buffering.
//  - consumer tile 6 ull x 2 slots (41 atom-pairs x 4 colgroups per half).
//  - consumer atom table pre-duplicated as ull (sA2d) -> no dup MOVs.

#define T36    36
#define TPAD   48
#define SAS    80      // float stride of atom export (40 cos | 40 sin)
#define NPAIR  48
#define NCOL   96
#define FDIM   20480
#define TOTCOL 40960
#define NITER  100
#define NTHREADS 512
#define SYS    50      // ull row stride (400B, 16B-aligned rows)
#define KOUT   161

typedef unsigned long long ull;

__device__ float g_A[T36 * SAS];   // normalized cos/sin atoms, t-major
__device__ float g_consts[2];      // {linv, lam}

// ---------------- packed f32x2 helpers ----------------
__device__ __forceinline__ void fma2(ull &d, ull a, ull b) {
    asm("fma.rn.f32x2 %0, %1, %2, %0;" : "+l"(d) : "l"(a), "l"(b));
}
__device__ __forceinline__ void add2(ull &d, ull a, ull b) {
    asm("add.rn.f32x2 %0, %1, %2;" : "=l"(d) : "l"(a), "l"(b));
}
__device__ __forceinline__ void mul2(ull &d, ull a, ull b) {
    asm("mul.rn.f32x2 %0, %1, %2;" : "=l"(d) : "l"(a), "l"(b));
}
__device__ __forceinline__ ull dup2(float x) {
    ull r; unsigned u = __float_as_uint(x);
    asm("mov.b64 %0, {%1, %1};" : "=l"(r) : "r"(u));
    return r;
}
__device__ __forceinline__ ull pack2(float a, float b) {
    ull r;
    asm("mov.b64 %0, {%1, %2};" : "=l"(r) : "f"(a), "f"(b));
    return r;
}
__device__ __forceinline__ float2 unpack2(ull v) {
    float2 r;
    asm("mov.b64 {%0, %1}, %2;" : "=f"(r.x), "=f"(r.y) : "l"(v));
    return r;
}

// =====================================================================
// Setup: normalized atoms + linv = 1/||D^T D||_F, lam = 0.1*linv
// =====================================================================
#define SETUP_T 256
#define KP 168
#define KREAL 161
__global__ void dyan_setup_kernel(const float* __restrict__ Drr,
                                  const float* __restrict__ Dtheta)
{
    __shared__ float  sDloc[T36 * KP];
    __shared__ double sred[SETUP_T];
    const int tid = threadIdx.x;

    for (int i = tid; i < T36 * KP; i += SETUP_T) sDloc[i] = 0.f;
    __syncthreads();

    for (int k = tid; k < KREAL; k += SETUP_T) {
        float col[T36];
        if (k == 0) {
            #pragma unroll
            for (int t = 0; t < T36; ++t) col[t] = 1.f;
        } else {
            const int grp = (k - 1) / 40;      // 0:rc 1:src 2:rs 3:srs
            const int nn  = (k - 1) % 40;
            const float r  = Drr[nn];
            const float th = Dtheta[nn];
            for (int t = 0; t < T36; ++t) {
                float ri   = powf(r, (float)t);
                float base = (grp < 2) ? cosf((float)t * th) : sinf((float)t * th);
                float v = ri * base;
                if ((grp & 1) && (t & 1)) v = -v;
                col[t] = v;
            }
        }
        float ss = 0.f;
        for (int t = 0; t < T36; ++t) ss += col[t] * col[t];
        float g = sqrtf(ss);
        if (g == 0.f) g = sqrtf((float)T36);
        for (int t = 0; t < T36; ++t) sDloc[t * KP + k] = col[t] / g;
    }
    __syncthreads();

    double acc = 0.0;
    for (int idx = tid; idx < KREAL * KREAL; idx += SETUP_T) {
        const int i = idx / KREAL, j = idx % KREAL;
        float d = 0.f;
        for (int t = 0; t < T36; ++t) d += sDloc[t * KP + i] * sDloc[t * KP + j];
        acc += (double)d * (double)d;
    }
    sred[tid] = acc;
    __syncthreads();
    for (int s = SETUP_T / 2; s > 0; s >>= 1) {
        if (tid < s) sred[tid] += sred[tid + s];
        __syncthreads();
    }
    if (tid == 0) {
        const float fro = (float)sqrt(sred[0]);
        g_consts[0] = 1.f / fro;
        g_consts[1] = 0.1f / fro;
    }
    // export normalized cos/sin atoms: g_A[t][n] = rc^, g_A[t][40+n] = rs^
    for (int i = tid; i < T36 * 40; i += SETUP_T) {
        const int t = i / 40, nn = i % 40;
        g_A[t * SAS + nn]      = sDloc[t * KP + 1 + nn];
        g_A[t * SAS + 40 + nn] = sDloc[t * KP + 81 + nn];
    }
}

// =====================================================================
// Main persistent FISTA kernel
//   Physical U row for slot (atom a = 2ng+s2): r = s2*40+ng.
//   SMEM: sU[160][SYS] (pq rows 0..79 | mn rows 80..159), sDtY[161][SYS]
//   (k>=1 at ab*80 + s2*40 + ng; k0 at row 160), sV[48][SYS], sY0[SYS],
//   sA1d[80][48] ull (phase-1, kk-major, permuted parity-packed, dup'd),
//   sA2d[36][80] ull (phase-2, t-major, dup'd).
// =====================================================================
__global__ void __launch_bounds__(NTHREADS, 1)
dyan_fista_kernel(const float* __restrict__ x, float* __restrict__ out)
{
    extern __shared__ unsigned char smraw[];
    ull* sU   = (ull*)smraw;              // 160*SYS
    ull* sDtY = sU   + 160 * SYS;         // 161*SYS
    ull* sV   = sDtY + 161 * SYS;         // 48*SYS
    ull* sY0  = sV   + TPAD * SYS;        // SYS
    ull* sA1d = sY0  + SYS;               // 80*48
    ull* sA2d = sA1d + SAS * 48;          // 36*80

    const int tid     = threadIdx.x;
    const int colBase = blockIdx.x * NCOL;
    const float linv = g_consts[0];
    const float lam  = g_consts[1];
    const float invs = 1.0f / 6.0f;
    const ull  neg1   = dup2(-1.f);
    const ull  half2  = dup2(0.5f);
    const ull  invs2  = dup2(invs);
    const ull  nlinv2 = dup2(-linv);

    // ---- stage atom tables ----
    for (int i = tid; i < SAS * 48; i += NTHREADS) {
        const int r = i / 48, c = i % 48;
        const int P = c / 24, j = c % 24;
        const int t = 2 * j + P;
        const int slot = (r < 40) ? 2 * r : 2 * (r - 40) + 1;   // sigma(r)
        sA1d[i] = (t < T36) ? dup2(g_A[t * SAS + slot]) : 0ull;
    }
    for (int i = tid; i < T36 * SAS; i += NTHREADS) {
        const int t = i / SAS, a = i % SAS;
        sA2d[t * SAS + a] = dup2(g_A[t * SAS + a]);
    }
    // ---- load Y into sV rows 0..35, zero pad rows ----
    for (int i = tid; i < TPAD * NPAIR; i += NTHREADS) {
        const int t = i / NPAIR, p = i % NPAIR;
        ull v = 0ull;
        const int c0 = colBase + 2 * p;
        if (t < T36 && c0 < TOTCOL) {
            const int b = c0 / FDIM, f = c0 % FDIM;
            const float2 yv = *(const float2*)(x + ((size_t)b * T36 + t) * FDIM + f);
            v = pack2(yv.x, yv.y);
        }
        sV[t * SYS + p] = v;
    }
    for (int i = tid; i < 160 * SYS; i += NTHREADS) sU[i] = 0ull;
    if (tid < SYS) sY0[tid] = 0ull;
    __syncthreads();

    // ---- role mapping ----
    const bool isProd = (tid < 128);
    // producer: warps 0-3; parity P1 = warp/2; within parity: 8 rg x 8 cg
    const int  P1  = (tid >> 6) & 1;
    const int  pid = tid & 63;
    const int  rjp = pid >> 3;            // 0..7 -> parity rows 3rjp..3rjp+2
    const int  cgp = pid & 7;             // 0..7 -> 3 ull at 3*cgp
    // consumer: warps 4-9 = group 0 (half A), warps 10-15 = group 1 (half B)
    const int  g    = (tid >= 320) ? 1 : 0;
    const int  ctid = isProd ? 0 : (tid - 128 - g * 192);  // 0..191
    const int  ng   = ctid % 41;
    const int  pgl  = ctid / 41;          // 0..4; active < 4
    const bool cact = (!isProd) && (pgl < 4);
    const bool creg = cact && (ng < 40);
    const bool ck0  = cact && (ng == 40);
    const int  hoff = g * 24 + 6 * pgl;   // ull col offset of this thread
    const ull* vP   = sV + hoff;
    const ull* a2p  = sA2d + 2 * ng;

    // ---- DtY init (consumers; sV holds Y) ----
    if (creg) {
        ull E[2][6] = {}, O[2][6] = {};
        #pragma unroll 6
        for (int tb = 0; tb < T36; tb += 2) {
            {   const ulonglong2 ad = *(const ulonglong2*)(a2p + (size_t)tb * SAS);
                const ull* vr = vP + (size_t)tb * SYS;
                const ulonglong2 v01 = *(const ulonglong2*)(vr);
                const ulonglong2 v23 = *(const ulonglong2*)(vr + 2);
                const ulonglong2 v45 = *(const ulonglong2*)(vr + 4);
                fma2(E[0][0],ad.x,v01.x); fma2(E[0][1],ad.x,v01.y);
                fma2(E[0][2],ad.x,v23.x); fma2(E[0][3],ad.x,v23.y);
                fma2(E[0][4],ad.x,v45.x); fma2(E[0][5],ad.x,v45.y);
                fma2(E[1][0],ad.y,v01.x); fma2(E[1][1],ad.y,v01.y);
                fma2(E[1][2],ad.y,v23.x); fma2(E[1][3],ad.y,v23.y);
                fma2(E[1][4],ad.y,v45.x); fma2(E[1][5],ad.y,v45.y);
            }
            {   const ulonglong2 ad = *(const ulonglong2*)(a2p + (size_t)(tb+1) * SAS);
                const ull* vr = vP + (size_t)(tb+1) * SYS;
                const ulonglong2 v01 = *(const ulonglong2*)(vr);
                const ulonglong2 v23 = *(const ulonglong2*)(vr + 2);
                const ulonglong2 v45 = *(const ulonglong2*)(vr + 4);
                fma2(O[0][0],ad.x,v01.x); fma2(O[0][1],ad.x,v01.y);
                fma2(O[0][2],ad.x,v23.x); fma2(O[0][3],ad.x,v23.y);
                fma2(O[0][4],ad.x,v45.x); fma2(O[0][5],ad.x,v45.y);
                fma2(O[1][0],ad.y,v01.x); fma2(O[1][1],ad.y,v01.y);
                fma2(O[1][2],ad.y,v23.x); fma2(O[1][3],ad.y,v23.y);
                fma2(O[1][4],ad.y,v45.x); fma2(O[1][5],ad.y,v45.y);
            }
        }
        const ull linv2 = dup2(linv);
        #pragma unroll
        for (int s2 = 0; s2 < 2; ++s2) {
            const int pr = s2 * 40 + ng;
            ull* da = sDtY + (size_t)pr * SYS + hoff;
            ull* db = sDtY + (size_t)(80 + pr) * SYS + hoff;
            #pragma unroll
            for (int j = 0; j < 6; ++j) {
                ull Sa; add2(Sa, E[s2][j], O[s2][j]); mul2(Sa, Sa, linv2); da[j] = Sa;
                ull Sb = E[s2][j]; fma2(Sb, neg1, O[s2][j]); mul2(Sb, Sb, linv2); db[j] = Sb;
            }
        }
    } else if (ck0) {
        ull T[6] = {};
        #pragma unroll 6
        for (int t = 0; t < T36; ++t) {
            const ull* vr = vP + (size_t)t * SYS;
            const ulonglong2 v01 = *(const ulonglong2*)(vr);
            const ulonglong2 v23 = *(const ulonglong2*)(vr + 2);
            const ulonglong2 v45 = *(const ulonglong2*)(vr + 4);
            add2(T[0], T[0], v01.x); add2(T[1], T[1], v01.y);
            add2(T[2], T[2], v23.x); add2(T[3], T[3], v23.y);
            add2(T[4], T[4], v45.x); add2(T[5], T[5], v45.y);
        }
        const ull sc = dup2(invs * linv);
        ull* d0 = sDtY + (size_t)160 * SYS + hoff;
        #pragma unroll
        for (int j = 0; j < 6; ++j) { ull s; mul2(s, T[j], sc); d0[j] = s; }
    }

    // ---- persistent state ----
    ull xold[2][2][6] = {};        // creg: [s2][a/b][j]
    ull x0r[6] = {}, y0r[6] = {};  // ck0
    float tcur = 1.f;

    __syncthreads();

    // ================= pipelined step loop =================
    // step s: producers compute V for half (s&1);
    //         consumer group g works when s>=1 and ((s-1)&1)==g.
    for (int s = 0; s < 2 * NITER + 1; ++s) {
        if (isProd) {
            if (s < 2 * NITER) {
                const int ho = (s & 1) * 24;
                ull vac[3][3];
                {   const ull* yp = sY0 + ho + 3 * cgp;
                    const ull y0v = yp[0], y1v = yp[1], y2v = yp[2];
                    vac[0][0]=y0v; vac[1][0]=y0v; vac[2][0]=y0v;
                    vac[0][1]=y1v; vac[1][1]=y1v; vac[2][1]=y1v;
                    vac[0][2]=y2v; vac[1][2]=y2v; vac[2][2]=y2v;
                }
                const ull* a1p = sA1d + P1 * 24 + 3 * rjp;
                const ull* ub  = sU + (size_t)(P1 * 80) * SYS + ho + 3 * cgp;
                #pragma unroll 8
                for (int kk = 0; kk < 80; ++kk) {
                    const ull* ak = a1p + kk * 48;
                    const ull d0 = ak[0], d1 = ak[1], d2 = ak[2];
                    const ull* ur = ub + (size_t)kk * SYS;
                    const ull u0 = ur[0], u1 = ur[1], u2 = ur[2];
                    fma2(vac[0][0],d0,u0); fma2(vac[0][1],d0,u1); fma2(vac[0][2],d0,u2);
                    fma2(vac[1][0],d1,u0); fma2(vac[1][1],d1,u1); fma2(vac[1][2],d1,u2);
                    fma2(vac[2][0],d2,u0); fma2(vac[2][1],d2,u1); fma2(vac[2][2],d2,u2);
                }
                #pragma unroll
                for (int r = 0; r < 3; ++r) {
                    const int t = 2 * (3 * rjp + r) + P1;
                    ull* vr = sV + (size_t)t * SYS + ho + 3 * cgp;
                    vr[0] = vac[r][0]; vr[1] = vac[r][1]; vr[2] = vac[r][2];
                }
            }
        } else if (cact && s >= 1 && ((s - 1) & 1) == g) {
            const float tnext = 0.5f * (1.f + sqrtf(fmaf(4.f * tcur, tcur, 1.f)));
            const float tt = (tcur - 1.f) / tnext;
            tcur = tnext;

            if (ng < 40) {
                ull E[2][6] = {}, O[2][6] = {};
                #pragma unroll 6
                for (int tb = 0; tb < T36; tb += 2) {
                    {   const ulonglong2 ad = *(const ulonglong2*)(a2p + (size_t)tb * SAS);
                        const ull* vr = vP + (size_t)tb * SYS;
                        const ulonglong2 v01 = *(const ulonglong2*)(vr);
                        const ulonglong2 v23 = *(const ulonglong2*)(vr + 2);
                        const ulonglong2 v45 = *(const ulonglong2*)(vr + 4);
                        fma2(E[0][0],ad.x,v01.x); fma2(E[0][1],ad.x,v01.y);
                        fma2(E[0][2],ad.x,v23.x); fma2(E[0][3],ad.x,v23.y);
                        fma2(E[0][4],ad.x,v45.x); fma2(E[0][5],ad.x,v45.y);
                        fma2(E[1][0],ad.y,v01.x); fma2(E[1][1],ad.y,v01.y);
                        fma2(E[1][2],ad.y,v23.x); fma2(E[1][3],ad.y,v23.y);
                        fma2(E[1][4],ad.y,v45.x); fma2(E[1][5],ad.y,v45.y);
                    }
                    {   const ulonglong2 ad = *(const ulonglong2*)(a2p + (size_t)(tb+1) * SAS);
                        const ull* vr = vP + (size_t)(tb+1) * SYS;
                        const ulonglong2 v01 = *(const ulonglong2*)(vr);
                        const ulonglong2 v23 = *(const ulonglong2*)(vr + 2);
                        const ulonglong2 v45 = *(const ulonglong2*)(vr + 4);
                        fma2(O[0][0],ad.x,v01.x); fma2(O[0][1],ad.x,v01.y);
                        fma2(O[0][2],ad.x,v23.x); fma2(O[0][3],ad.x,v23.y);
                        fma2(O[0][4],ad.x,v45.x); fma2(O[0][5],ad.x,v45.y);
                        fma2(O[1][0],ad.y,v01.x); fma2(O[1][1],ad.y,v01.y);
                        fma2(O[1][2],ad.y,v23.x); fma2(O[1][3],ad.y,v23.y);
                        fma2(O[1][4],ad.y,v45.x); fma2(O[1][5],ad.y,v45.y);
                    }
                }
                #pragma unroll
                for (int s2 = 0; s2 < 2; ++s2) {
                    const int pr = s2 * 40 + ng;
                    ull* Up = sU + (size_t)pr * SYS + hoff;
                    ull* Um = sU + (size_t)(80 + pr) * SYS + hoff;
                    const ull* Da = sDtY + (size_t)pr * SYS + hoff;
                    const ull* Db = sDtY + (size_t)(80 + pr) * SYS + hoff;
                    ull pn[6], mn[6];
                    #pragma unroll
                    for (int jq = 0; jq < 3; ++jq) {
                        const ulonglong2 up2 = *(const ulonglong2*)(Up + 2 * jq);
                        const ulonglong2 um2 = *(const ulonglong2*)(Um + 2 * jq);
                        const ulonglong2 da2 = *(const ulonglong2*)(Da + 2 * jq);
                        const ulonglong2 db2 = *(const ulonglong2*)(Db + 2 * jq);
                        const ull ups[2] = {up2.x, up2.y};
                        const ull ums[2] = {um2.x, um2.y};
                        const ull das[2] = {da2.x, da2.y};
                        const ull dbs[2] = {db2.x, db2.y};
                        #pragma unroll
                        for (int q = 0; q < 2; ++q) {
                            const int j = 2 * jq + q;
                            ull ya; add2(ya, ups[q], ums[q]); mul2(ya, ya, half2);
                            ull yb = ups[q]; fma2(yb, neg1, ums[q]); mul2(yb, yb, half2);
                            ull Sa; add2(Sa, E[s2][j], O[s2][j]);
                            ull Sb = E[s2][j]; fma2(Sb, neg1, O[s2][j]);
                            ull ra = ya; fma2(ra, nlinv2, Sa); add2(ra, ra, das[q]);
                            ull rb = yb; fma2(rb, nlinv2, Sb); add2(rb, rb, dbs[q]);
                            const float2 fa = unpack2(ra);
                            const float xa0 = copysignf(fmaxf(fabsf(fa.x) - lam, 0.f), fa.x);
                            const float xa1 = copysignf(fmaxf(fabsf(fa.y) - lam, 0.f), fa.y);
                            const float2 xoa = unpack2(xold[s2][0][j]);
                            const float yna0 = fmaf(tt, xa0 - xoa.x, xa0);
                            const float yna1 = fmaf(tt, xa1 - xoa.y, xa1);
                            xold[s2][0][j] = pack2(xa0, xa1);
                            const ull yna = pack2(yna0, yna1);
                            const float2 fb = unpack2(rb);
                            const float xb0 = copysignf(fmaxf(fabsf(fb.x) - lam, 0.f), fb.x);
                            const float xb1 = copysignf(fmaxf(fabsf(fb.y) - lam, 0.f), fb.y);
                            const float2 xob = unpack2(xold[s2][1][j]);
                            const float ynb0 = fmaf(tt, xb0 - xob.x, xb0);
                            const float ynb1 = fmaf(tt, xb1 - xob.y, xb1);
                            xold[s2][1][j] = pack2(xb0, xb1);
                            const ull ynb = pack2(ynb0, ynb1);
                            add2(pn[j], yna, ynb);
                            mn[j] = yna; fma2(mn[j], neg1, ynb);
                        }
                    }
                    #pragma unroll
                    for (int jq = 0; jq < 3; ++jq) {
                        ulonglong2 pw; pw.x = pn[2*jq]; pw.y = pn[2*jq+1];
                        ulonglong2 mw; mw.x = mn[2*jq]; mw.y = mn[2*jq+1];
                        *(ulonglong2*)(Up + 2 * jq) = pw;
                        *(ulonglong2*)(Um + 2 * jq) = mw;
                    }
                }
            } else {   // k0 (ones atom)
                ull T[6] = {};
                #pragma unroll 6
                for (int t = 0; t < T36; ++t) {
                    const ull* vr = vP + (size_t)t * SYS;
                    const ulonglong2 v01 = *(const ulonglong2*)(vr);
                    const ulonglong2 v23 = *(const ulonglong2*)(vr + 2);
                    const ulonglong2 v45 = *(const ulonglong2*)(vr + 4);
                    add2(T[0], T[0], v01.x); add2(T[1], T[1], v01.y);
                    add2(T[2], T[2], v23.x); add2(T[3], T[3], v23.y);
                    add2(T[4], T[4], v45.x); add2(T[5], T[5], v45.y);
                }
                const ull* D0 = sDtY + (size_t)160 * SYS + hoff;
                #pragma unroll
                for (int j = 0; j < 6; ++j) {
                    ull S; mul2(S, T[j], invs2);
                    ull r = y0r[j]; fma2(r, nlinv2, S); add2(r, r, D0[j]);
                    const float2 fr = unpack2(r);
                    const float x0 = copysignf(fmaxf(fabsf(fr.x) - lam, 0.f), fr.x);
                    const float x1 = copysignf(fmaxf(fabsf(fr.y) - lam, 0.f), fr.y);
                    const float2 xo = unpack2(x0r[j]);
                    const float yn0 = fmaf(tt, x0 - xo.x, x0);
                    const float yn1 = fmaf(tt, x1 - xo.y, x1);
                    x0r[j] = pack2(x0, x1);
                    y0r[j] = pack2(yn0, yn1);
                    ull ys; mul2(ys, y0r[j], invs2);
                    sY0[hoff + j] = ys;
                }
            }
        }
        __syncthreads();
    }

    // ---- write final x (xold) straight to GMEM ----
    if (creg) {
        #pragma unroll
        for (int s2 = 0; s2 < 2; ++s2) {
            const int slot = 2 * ng + s2;
            const int ka = (slot < 40) ? 1 + slot : 41 + slot;
            const int kb = ka + 40;
            #pragma unroll
            for (int j = 0; j < 6; ++j) {
                const int c0 = colBase + 2 * (hoff + j);
                if (c0 < TOTCOL) {
                    const int b = c0 / FDIM, f = c0 % FDIM;
                    *(float2*)(out + ((size_t)b * KOUT + ka) * FDIM + f) = unpack2(xold[s2][0][j]);
                    *(float2*)(out + ((size_t)b * KOUT + kb) * FDIM + f) = unpack2(xold[s2][1][j]);
                }
            }
        }
    } else if (ck0) {
        #pragma unroll
        for (int j = 0; j < 6; ++j) {
            const int c0 = colBase + 2 * (hoff + j);
            if (c0 < TOTCOL) {
                const int b = c0 / FDIM, f = c0 % FDIM;
                *(float2*)(out + ((size_t)b * KOUT + 0) * FDIM + f) = unpack2(x0r[j]);
            }
        }
    }
}

// =====================================================================
extern "C" void kernel_launch(void* const* d_in, const int* in_sizes, int n_in,
                              void* d_out, int out_size)
{
    const float* x   = (const float*)d_in[0];
    const float* drr = (const float*)d_in[1];
    const float* dth = (const float*)d_in[2];
    float* out = (float*)d_out;
    (void)in_sizes; (void)n_in; (void)out_size;

    const size_t smem = (size_t)(160 * SYS + 161 * SYS + TPAD * SYS + SYS
                                 + SAS * 48 + T36 * SAS) * sizeof(ull);  // 201,760 B

    cudaFuncSetAttribute(dyan_fista_kernel,
                         cudaFuncAttributeMaxDynamicSharedMemorySize, (int)smem);

    dyan_setup_kernel<<<1, SETUP_T>>>(drr, dth);

    const int grid = (TOTCOL + NCOL - 1) / NCOL;   // 427
    dyan_fista_kernel<<<grid, NTHREADS, smem>>>(x, out);
}